// round 1
// baseline (speedup 1.0000x reference)
#include <cuda_runtime.h>

#define SQ   2048
#define ED   2048
#define NH   16
#define NG   32      // 2*H query/key heads
#define HDIM 64      // differential head dim
#define VDIM 128     // value head dim (2*HD)

static constexpr float LAMBDA_INIT = 0.78360576653162444f;

// ---- device scratch (static: no runtime allocation allowed) ----
__device__ float g_Q[SQ * ED];
__device__ float g_K[SQ * ED];
__device__ float g_V[SQ * ED];
__device__ float g_O[NG * SQ * VDIM];   // per-QK-head attention outputs
__device__ float g_X[SQ * ED];          // combined/normalized attention (S, E)
__device__ float g_lam;

// ============================================================================
// GEMM (NT): C[m,n] = sum_k A[m,k] * W[n,k], M=N=K=2048
// 128x128 tile, TK=8, 256 threads, 8x8 per thread.
// a_tag: 0 -> A = Aext, 1 -> A = g_X
// c_tag: 0 -> C = Cext, 1 -> g_Q, 2 -> g_K, 3 -> g_V
// ============================================================================
__global__ __launch_bounds__(256) void gemm_nt(const float* __restrict__ Aext,
                                               const float* __restrict__ W,
                                               float* __restrict__ Cext,
                                               int a_tag, int c_tag)
{
    const float* A = (a_tag == 0) ? Aext : g_X;
    float* C = Cext;
    if (c_tag == 1) C = g_Q;
    else if (c_tag == 2) C = g_K;
    else if (c_tag == 3) C = g_V;

    __shared__ float As[8][128];
    __shared__ float Bs[8][128];

    const int t    = threadIdx.x;
    const int m0   = blockIdx.y * 128;
    const int n0   = blockIdx.x * 128;
    const int r0   = (t >> 4) * 8;
    const int c0   = (t & 15) * 8;
    const int lrow = t >> 1;
    const int lseg = (t & 1) * 4;

    float acc[8][8];
    #pragma unroll
    for (int i = 0; i < 8; i++)
        #pragma unroll
        for (int j = 0; j < 8; j++) acc[i][j] = 0.f;

    const float* Ap = A + (m0 + lrow) * ED + lseg;
    const float* Wp = W + (n0 + lrow) * ED + lseg;

    for (int k0 = 0; k0 < ED; k0 += 8) {
        float4 av = *(const float4*)(Ap + k0);
        float4 bv = *(const float4*)(Wp + k0);
        __syncthreads();
        As[lseg + 0][lrow] = av.x; As[lseg + 1][lrow] = av.y;
        As[lseg + 2][lrow] = av.z; As[lseg + 3][lrow] = av.w;
        Bs[lseg + 0][lrow] = bv.x; Bs[lseg + 1][lrow] = bv.y;
        Bs[lseg + 2][lrow] = bv.z; Bs[lseg + 3][lrow] = bv.w;
        __syncthreads();
        #pragma unroll
        for (int k = 0; k < 8; k++) {
            float4 aA = *(const float4*)&As[k][r0];
            float4 aB = *(const float4*)&As[k][r0 + 4];
            float4 bA = *(const float4*)&Bs[k][c0];
            float4 bB = *(const float4*)&Bs[k][c0 + 4];
            float a[8], b[8];
            a[0]=aA.x; a[1]=aA.y; a[2]=aA.z; a[3]=aA.w;
            a[4]=aB.x; a[5]=aB.y; a[6]=aB.z; a[7]=aB.w;
            b[0]=bA.x; b[1]=bA.y; b[2]=bA.z; b[3]=bA.w;
            b[4]=bB.x; b[5]=bB.y; b[6]=bB.z; b[7]=bB.w;
            #pragma unroll
            for (int i = 0; i < 8; i++)
                #pragma unroll
                for (int j = 0; j < 8; j++)
                    acc[i][j] += a[i] * b[j];
        }
    }

    #pragma unroll
    for (int i = 0; i < 8; i++) {
        float* crow = C + (m0 + r0 + i) * ED + n0 + c0;
        float4 o0 = make_float4(acc[i][0], acc[i][1], acc[i][2], acc[i][3]);
        float4 o1 = make_float4(acc[i][4], acc[i][5], acc[i][6], acc[i][7]);
        *(float4*)crow       = o0;
        *(float4*)(crow + 4) = o1;
    }
}

// ============================================================================
// lambda_full = exp(sum(lq1*lk1)) - exp(sum(lq2*lk2)) + LAMBDA_INIT
// ============================================================================
__global__ void lam_kernel(const float* __restrict__ lq1, const float* __restrict__ lk1,
                           const float* __restrict__ lq2, const float* __restrict__ lk2)
{
    int lane = threadIdx.x;  // 64 threads
    float p1 = lq1[lane] * lk1[lane];
    float p2 = lq2[lane] * lk2[lane];
    #pragma unroll
    for (int o = 16; o > 0; o >>= 1) {
        p1 += __shfl_xor_sync(0xffffffffu, p1, o);
        p2 += __shfl_xor_sync(0xffffffffu, p2, o);
    }
    __shared__ float s1w[2], s2w[2];
    if ((lane & 31) == 0) { s1w[lane >> 5] = p1; s2w[lane >> 5] = p2; }
    __syncthreads();
    if (lane == 0)
        g_lam = expf(s1w[0] + s1w[1]) - expf(s2w[0] + s2w[1]) + LAMBDA_INIT;
}

// ============================================================================
// Flash-style attention per QK-head g (0..31):
//   O[g] = softmax( (Q_g * hd^-0.5) K_g^T + mask ) @ V_{g/2}
// Block: 64 query rows, streams K/V in 64-row tiles. 256 threads.
// ============================================================================
__global__ __launch_bounds__(256) void attn_kernel(const unsigned char* __restrict__ mask)
{
    extern __shared__ float sm[];
    float* Qs   = sm;                 // 64 x 68 (padded)
    float* Ks   = Qs + 64 * 68;       // 64 x 68
    float* Ps   = Ks + 64 * 68;       // 64 x 68
    float* Vs   = Ps + 64 * 68;       // 64 x 128
    float* mrow = Vs + 64 * 128;      // 64
    float* lrow = mrow + 64;          // 64
    float* sfac = lrow + 64;          // 64

    const int g  = blockIdx.y;
    const int h  = g >> 1;
    const int q0 = blockIdx.x * 64;
    const int t  = threadIdx.x;

    // load Q tile (scaled by hd^-0.5 = 0.125)
    for (int i = t; i < 64 * 16; i += 256) {
        int r = i >> 4, c4 = (i & 15) * 4;
        float4 v = *(const float4*)&g_Q[(q0 + r) * ED + g * HDIM + c4];
        float* dst = &Qs[r * 68 + c4];
        dst[0] = v.x * 0.125f; dst[1] = v.y * 0.125f;
        dst[2] = v.z * 0.125f; dst[3] = v.w * 0.125f;
    }
    if (t < 64) { mrow[t] = -1e30f; lrow[t] = 0.f; }

    float acc[32];
    #pragma unroll
    for (int i = 0; i < 32; i++) acc[i] = 0.f;

    const int d    = t & 127;            // output column
    const int rg   = (t >> 7) * 32;      // output row group
    const int sr0  = (t >> 4) * 4;       // score micro-tile row
    const int sj0  = (t & 15) * 4;       // score micro-tile col
    const int srow = t >> 2;             // softmax row
    const int sq4  = (t & 3) * 16;       // softmax quarter

    for (int kt = 0; kt < SQ; kt += 64) {
        __syncthreads();
        // load K tile
        for (int i = t; i < 64 * 16; i += 256) {
            int r = i >> 4, c4 = (i & 15) * 4;
            float4 v = *(const float4*)&g_K[(kt + r) * ED + g * HDIM + c4];
            float* dst = &Ks[r * 68 + c4];
            dst[0] = v.x; dst[1] = v.y; dst[2] = v.z; dst[3] = v.w;
        }
        // load V tile
        for (int i = t; i < 64 * 32; i += 256) {
            int r = i >> 5, c4 = (i & 31) * 4;
            *(float4*)&Vs[r * VDIM + c4] =
                *(const float4*)&g_V[(kt + r) * ED + h * VDIM + c4];
        }
        __syncthreads();

        // scores: 4x4 micro-tile per thread over 64-dim dot
        float sc[4][4];
        #pragma unroll
        for (int i = 0; i < 4; i++)
            #pragma unroll
            for (int j = 0; j < 4; j++) sc[i][j] = 0.f;
        #pragma unroll
        for (int d4 = 0; d4 < 16; d4++) {
            float4 qv[4], kv[4];
            #pragma unroll
            for (int i = 0; i < 4; i++) qv[i] = *(const float4*)&Qs[(sr0 + i) * 68 + d4 * 4];
            #pragma unroll
            for (int j = 0; j < 4; j++) kv[j] = *(const float4*)&Ks[(sj0 + j) * 68 + d4 * 4];
            #pragma unroll
            for (int i = 0; i < 4; i++)
                #pragma unroll
                for (int j = 0; j < 4; j++)
                    sc[i][j] += qv[i].x * kv[j].x + qv[i].y * kv[j].y +
                                qv[i].z * kv[j].z + qv[i].w * kv[j].w;
        }
        #pragma unroll
        for (int j = 0; j < 4; j++) {
            bool msk = mask[kt + sj0 + j] != 0;
            #pragma unroll
            for (int i = 0; i < 4; i++)
                Ps[(sr0 + i) * 68 + sj0 + j] = msk ? -1e30f : sc[i][j];
        }
        __syncthreads();

        // online softmax: 4 threads cooperate per row
        {
            float m_old = mrow[srow];
            float mx = -1e30f;
            #pragma unroll
            for (int j = 0; j < 16; j++) mx = fmaxf(mx, Ps[srow * 68 + sq4 + j]);
            mx = fmaxf(mx, __shfl_xor_sync(0xffffffffu, mx, 1));
            mx = fmaxf(mx, __shfl_xor_sync(0xffffffffu, mx, 2));
            float mnew = fmaxf(m_old, mx);
            float sum = 0.f;
            #pragma unroll
            for (int j = 0; j < 16; j++) {
                float p = __expf(Ps[srow * 68 + sq4 + j] - mnew);
                Ps[srow * 68 + sq4 + j] = p;
                sum += p;
            }
            sum += __shfl_xor_sync(0xffffffffu, sum, 1);
            sum += __shfl_xor_sync(0xffffffffu, sum, 2);
            if ((t & 3) == 0) {
                float scale = __expf(m_old - mnew);
                lrow[srow] = lrow[srow] * scale + sum;
                mrow[srow] = mnew;
                sfac[srow] = scale;
            }
        }
        __syncthreads();

        // acc = acc*scale + P @ V  (thread owns column d, rows rg..rg+31)
        #pragma unroll
        for (int r = 0; r < 32; r++) acc[r] *= sfac[rg + r];
        #pragma unroll 4
        for (int j4 = 0; j4 < 16; j4++) {
            float vv0 = Vs[(j4 * 4 + 0) * VDIM + d];
            float vv1 = Vs[(j4 * 4 + 1) * VDIM + d];
            float vv2 = Vs[(j4 * 4 + 2) * VDIM + d];
            float vv3 = Vs[(j4 * 4 + 3) * VDIM + d];
            #pragma unroll
            for (int r = 0; r < 32; r++) {
                float4 p = *(const float4*)&Ps[(rg + r) * 68 + j4 * 4];
                acc[r] += p.x * vv0 + p.y * vv1 + p.z * vv2 + p.w * vv3;
            }
        }
    }

    #pragma unroll
    for (int r = 0; r < 32; r++) {
        float l = lrow[rg + r];
        g_O[(g * SQ + q0 + rg + r) * VDIM + d] = acc[r] / l;
    }
}

// ============================================================================
// Epilogue: x = O[2h] - lam*O[2h+1]; RMSNorm over 128; * subln_g * (1-lam_init)
// grid (S, H), 128 threads
// ============================================================================
__global__ __launch_bounds__(128) void epi_kernel(const float* __restrict__ subg)
{
    const int s = blockIdx.x, h = blockIdx.y, d = threadIdx.x;
    const float lam = g_lam;
    float a = g_O[((2 * h) * SQ + s) * VDIM + d];
    float b = g_O[((2 * h + 1) * SQ + s) * VDIM + d];
    float x = a - lam * b;

    float v = x * x;
    #pragma unroll
    for (int o = 16; o > 0; o >>= 1) v += __shfl_xor_sync(0xffffffffu, v, o);
    __shared__ float ws[4];
    if ((d & 31) == 0) ws[d >> 5] = v;
    __syncthreads();
    float tot = ws[0] + ws[1] + ws[2] + ws[3];
    float rms = rsqrtf(tot * (1.f / 128.f) + 1e-5f);

    g_X[s * ED + h * VDIM + d] = x * rms * subg[d] * (1.f - LAMBDA_INIT);
}

// ============================================================================
// launch
// ============================================================================
extern "C" void kernel_launch(void* const* d_in, const int* in_sizes, int n_in,
                              void* d_out, int out_size)
{
    (void)in_sizes; (void)n_in; (void)out_size;
    const float* query = (const float*)d_in[0];
    const float* key   = (const float*)d_in[1];
    const float* value = (const float*)d_in[2];
    // d_in[3] = rel_pos (unused, always 0)
    const unsigned char* mask = (const unsigned char*)d_in[4];
    const float* Wq  = (const float*)d_in[5];
    const float* Wk  = (const float*)d_in[6];
    const float* Wv  = (const float*)d_in[7];
    const float* Wo  = (const float*)d_in[8];
    const float* lq1 = (const float*)d_in[9];
    const float* lk1 = (const float*)d_in[10];
    const float* lq2 = (const float*)d_in[11];
    const float* lk2 = (const float*)d_in[12];
    const float* subg = (const float*)d_in[13];
    float* out = (float*)d_out;

    const int attn_smem = (3 * 64 * 68 + 64 * 128 + 3 * 64) * (int)sizeof(float); // 85760
    cudaFuncSetAttribute(attn_kernel, cudaFuncAttributeMaxDynamicSharedMemorySize, attn_smem);

    dim3 gblk(16, 16);
    gemm_nt<<<gblk, 256>>>(query, Wq, nullptr, 0, 1);
    gemm_nt<<<gblk, 256>>>(key,   Wk, nullptr, 0, 2);
    gemm_nt<<<gblk, 256>>>(value, Wv, nullptr, 0, 3);
    lam_kernel<<<1, 64>>>(lq1, lk1, lq2, lk2);
    attn_kernel<<<dim3(32, 32), 256, attn_smem>>>(mask);
    epi_kernel<<<dim3(SQ, NH), 128>>>(subg);
    gemm_nt<<<gblk, 256>>>(nullptr, Wo, out, 1, 0);
}

// round 2
// speedup vs baseline: 1.4358x; 1.4358x over previous
#include <cuda_runtime.h>

#define SQ   2048
#define ED   2048
#define NH   16
#define NG   32      // 2*H query/key heads
#define HDIM 64      // differential head dim
#define VDIM 128     // value head dim (2*HD)

static constexpr float LAMBDA_INIT = 0.78360576653162444f;

// ---- device scratch (static: no runtime allocation allowed) ----
__device__ float g_Q[SQ * ED];
__device__ float g_K[SQ * ED];
__device__ float g_V[SQ * ED];
__device__ float g_O[NG * SQ * VDIM];   // per-QK-head attention outputs
__device__ float g_X[SQ * ED];          // combined/normalized attention (S, E)
__device__ float g_lam;

__device__ __forceinline__ unsigned f2tf(float x) {
    unsigned r;
    asm("cvt.rna.tf32.f32 %0, %1;" : "=r"(r) : "f"(x));
    return r;
}

__device__ __forceinline__ void mma_tf32(float c[4], const unsigned a[4], const unsigned b[2]) {
    asm volatile(
        "mma.sync.aligned.m16n8k8.row.col.f32.tf32.tf32.f32 "
        "{%0,%1,%2,%3}, {%4,%5,%6,%7}, {%8,%9}, {%0,%1,%2,%3};"
        : "+f"(c[0]), "+f"(c[1]), "+f"(c[2]), "+f"(c[3])
        : "r"(a[0]), "r"(a[1]), "r"(a[2]), "r"(a[3]), "r"(b[0]), "r"(b[1]));
}

// ============================================================================
// TF32 tensor-core GEMM (NT): C[m,n] = sum_k A[m,k] * W[n,k], M=N=K=2048
// 128x128x32 block tile, 8 warps (2x4), each warp 64x32 via m16n8k8 atoms.
// a_tag: 0 -> A = Aext, 1 -> A = g_X
// c_tag: 0 -> C = Cext, 1 -> g_Q, 2 -> g_K, 3 -> g_V
// ============================================================================
__global__ __launch_bounds__(256) void gemm_nt(const float* __restrict__ Aext,
                                               const float* __restrict__ W,
                                               float* __restrict__ Cext,
                                               int a_tag, int c_tag)
{
    const float* A = (a_tag == 0) ? Aext : g_X;
    float* C = Cext;
    if (c_tag == 1) C = g_Q;
    else if (c_tag == 2) C = g_K;
    else if (c_tag == 3) C = g_V;

    // pad 36: fragment reads hit bank (4*grp + qid) % 32 -> conflict-free
    __shared__ unsigned As[128][36];
    __shared__ unsigned Bs[128][36];

    const int t    = threadIdx.x;
    const int m0   = blockIdx.y * 128;
    const int n0   = blockIdx.x * 128;
    const int wid  = t >> 5;
    const int lane = t & 31;
    const int wm   = (wid >> 2) * 64;   // warp row offset in tile
    const int wn   = (wid & 3) * 32;    // warp col offset in tile
    const int grp  = lane >> 2;         // 0..7
    const int qid  = lane & 3;          // 0..3

    float acc[4][4][4];
    #pragma unroll
    for (int mi = 0; mi < 4; mi++)
        #pragma unroll
        for (int ni = 0; ni < 4; ni++)
            #pragma unroll
            for (int x = 0; x < 4; x++) acc[mi][ni][x] = 0.f;

    float4 ra[4], rb[4];

    // prefetch first k-tile
    #pragma unroll
    for (int i = 0; i < 4; i++) {
        int lin = t + 256 * i;
        int r = lin >> 3, c = (lin & 7) * 4;
        ra[i] = *(const float4*)(A + (m0 + r) * ED + c);
        rb[i] = *(const float4*)(W + (n0 + r) * ED + c);
    }

    const int NT = ED / 32;   // 64 k-tiles
    for (int kt = 0; kt < NT; kt++) {
        // stage current tile into smem (tf32-converted)
        #pragma unroll
        for (int i = 0; i < 4; i++) {
            int lin = t + 256 * i;
            int r = lin >> 3, c = (lin & 7) * 4;
            As[r][c + 0] = f2tf(ra[i].x); As[r][c + 1] = f2tf(ra[i].y);
            As[r][c + 2] = f2tf(ra[i].z); As[r][c + 3] = f2tf(ra[i].w);
            Bs[r][c + 0] = f2tf(rb[i].x); Bs[r][c + 1] = f2tf(rb[i].y);
            Bs[r][c + 2] = f2tf(rb[i].z); Bs[r][c + 3] = f2tf(rb[i].w);
        }
        __syncthreads();

        // prefetch next tile while computing
        if (kt + 1 < NT) {
            int k0 = (kt + 1) * 32;
            #pragma unroll
            for (int i = 0; i < 4; i++) {
                int lin = t + 256 * i;
                int r = lin >> 3, c = (lin & 7) * 4;
                ra[i] = *(const float4*)(A + (m0 + r) * ED + k0 + c);
                rb[i] = *(const float4*)(W + (n0 + r) * ED + k0 + c);
            }
        }

        #pragma unroll
        for (int ks = 0; ks < 4; ks++) {
            unsigned af[4][4], bf[4][2];
            #pragma unroll
            for (int mi = 0; mi < 4; mi++) {
                int r = wm + mi * 16 + grp;
                af[mi][0] = As[r][ks * 8 + qid];
                af[mi][1] = As[r + 8][ks * 8 + qid];
                af[mi][2] = As[r][ks * 8 + qid + 4];
                af[mi][3] = As[r + 8][ks * 8 + qid + 4];
            }
            #pragma unroll
            for (int ni = 0; ni < 4; ni++) {
                int r = wn + ni * 8 + grp;
                bf[ni][0] = Bs[r][ks * 8 + qid];
                bf[ni][1] = Bs[r][ks * 8 + qid + 4];
            }
            #pragma unroll
            for (int mi = 0; mi < 4; mi++)
                #pragma unroll
                for (int ni = 0; ni < 4; ni++)
                    mma_tf32(acc[mi][ni], af[mi], bf[ni]);
        }
        __syncthreads();
    }

    // epilogue: c0,c1 at (grp, 2*qid), c2,c3 at (grp+8, 2*qid)
    #pragma unroll
    for (int mi = 0; mi < 4; mi++) {
        #pragma unroll
        for (int ni = 0; ni < 4; ni++) {
            int row = m0 + wm + mi * 16 + grp;
            int col = n0 + wn + ni * 8 + 2 * qid;
            *(float2*)&C[row * ED + col]       = make_float2(acc[mi][ni][0], acc[mi][ni][1]);
            *(float2*)&C[(row + 8) * ED + col] = make_float2(acc[mi][ni][2], acc[mi][ni][3]);
        }
    }
}

// ============================================================================
// lambda_full = exp(sum(lq1*lk1)) - exp(sum(lq2*lk2)) + LAMBDA_INIT
// ============================================================================
__global__ void lam_kernel(const float* __restrict__ lq1, const float* __restrict__ lk1,
                           const float* __restrict__ lq2, const float* __restrict__ lk2)
{
    int lane = threadIdx.x;  // 64 threads
    float p1 = lq1[lane] * lk1[lane];
    float p2 = lq2[lane] * lk2[lane];
    #pragma unroll
    for (int o = 16; o > 0; o >>= 1) {
        p1 += __shfl_xor_sync(0xffffffffu, p1, o);
        p2 += __shfl_xor_sync(0xffffffffu, p2, o);
    }
    __shared__ float s1w[2], s2w[2];
    if ((lane & 31) == 0) { s1w[lane >> 5] = p1; s2w[lane >> 5] = p2; }
    __syncthreads();
    if (lane == 0)
        g_lam = expf(s1w[0] + s1w[1]) - expf(s2w[0] + s2w[1]) + LAMBDA_INIT;
}

// ============================================================================
// Flash-style attention per QK-head g (0..31):
//   O[g] = softmax( (Q_g * hd^-0.5) K_g^T + mask ) @ V_{g/2}
// Block: 64 query rows, streams K/V in 64-row tiles. 256 threads.
// ============================================================================
__global__ __launch_bounds__(256) void attn_kernel(const unsigned char* __restrict__ mask)
{
    extern __shared__ float sm[];
    float* Qs   = sm;                 // 64 x 68 (padded)
    float* Ks   = Qs + 64 * 68;       // 64 x 68
    float* Ps   = Ks + 64 * 68;       // 64 x 68
    float* Vs   = Ps + 64 * 68;       // 64 x 128
    float* mrow = Vs + 64 * 128;      // 64
    float* lrow = mrow + 64;          // 64
    float* sfac = lrow + 64;          // 64

    const int g  = blockIdx.y;
    const int h  = g >> 1;
    const int q0 = blockIdx.x * 64;
    const int t  = threadIdx.x;

    // load Q tile (scaled by hd^-0.5 = 0.125)
    for (int i = t; i < 64 * 16; i += 256) {
        int r = i >> 4, c4 = (i & 15) * 4;
        float4 v = *(const float4*)&g_Q[(q0 + r) * ED + g * HDIM + c4];
        float* dst = &Qs[r * 68 + c4];
        dst[0] = v.x * 0.125f; dst[1] = v.y * 0.125f;
        dst[2] = v.z * 0.125f; dst[3] = v.w * 0.125f;
    }
    if (t < 64) { mrow[t] = -1e30f; lrow[t] = 0.f; }

    float acc[32];
    #pragma unroll
    for (int i = 0; i < 32; i++) acc[i] = 0.f;

    const int d    = t & 127;            // output column
    const int rg   = (t >> 7) * 32;      // output row group
    const int sr0  = (t >> 4) * 4;       // score micro-tile row
    const int sj0  = (t & 15) * 4;       // score micro-tile col
    const int srow = t >> 2;             // softmax row
    const int sq4  = (t & 3) * 16;       // softmax quarter

    for (int kt = 0; kt < SQ; kt += 64) {
        __syncthreads();
        // load K tile
        for (int i = t; i < 64 * 16; i += 256) {
            int r = i >> 4, c4 = (i & 15) * 4;
            float4 v = *(const float4*)&g_K[(kt + r) * ED + g * HDIM + c4];
            float* dst = &Ks[r * 68 + c4];
            dst[0] = v.x; dst[1] = v.y; dst[2] = v.z; dst[3] = v.w;
        }
        // load V tile
        for (int i = t; i < 64 * 32; i += 256) {
            int r = i >> 5, c4 = (i & 31) * 4;
            *(float4*)&Vs[r * VDIM + c4] =
                *(const float4*)&g_V[(kt + r) * ED + h * VDIM + c4];
        }
        __syncthreads();

        // scores: 4x4 micro-tile per thread over 64-dim dot
        float sc[4][4];
        #pragma unroll
        for (int i = 0; i < 4; i++)
            #pragma unroll
            for (int j = 0; j < 4; j++) sc[i][j] = 0.f;
        #pragma unroll
        for (int d4 = 0; d4 < 16; d4++) {
            float4 qv[4], kv[4];
            #pragma unroll
            for (int i = 0; i < 4; i++) qv[i] = *(const float4*)&Qs[(sr0 + i) * 68 + d4 * 4];
            #pragma unroll
            for (int j = 0; j < 4; j++) kv[j] = *(const float4*)&Ks[(sj0 + j) * 68 + d4 * 4];
            #pragma unroll
            for (int i = 0; i < 4; i++)
                #pragma unroll
                for (int j = 0; j < 4; j++)
                    sc[i][j] += qv[i].x * kv[j].x + qv[i].y * kv[j].y +
                                qv[i].z * kv[j].z + qv[i].w * kv[j].w;
        }
        #pragma unroll
        for (int j = 0; j < 4; j++) {
            bool msk = mask[kt + sj0 + j] != 0;
            #pragma unroll
            for (int i = 0; i < 4; i++)
                Ps[(sr0 + i) * 68 + sj0 + j] = msk ? -1e30f : sc[i][j];
        }
        __syncthreads();

        // online softmax: 4 threads cooperate per row
        {
            float m_old = mrow[srow];
            float mx = -1e30f;
            #pragma unroll
            for (int j = 0; j < 16; j++) mx = fmaxf(mx, Ps[srow * 68 + sq4 + j]);
            mx = fmaxf(mx, __shfl_xor_sync(0xffffffffu, mx, 1));
            mx = fmaxf(mx, __shfl_xor_sync(0xffffffffu, mx, 2));
            float mnew = fmaxf(m_old, mx);
            float sum = 0.f;
            #pragma unroll
            for (int j = 0; j < 16; j++) {
                float p = __expf(Ps[srow * 68 + sq4 + j] - mnew);
                Ps[srow * 68 + sq4 + j] = p;
                sum += p;
            }
            sum += __shfl_xor_sync(0xffffffffu, sum, 1);
            sum += __shfl_xor_sync(0xffffffffu, sum, 2);
            if ((t & 3) == 0) {
                float scale = __expf(m_old - mnew);
                lrow[srow] = lrow[srow] * scale + sum;
                mrow[srow] = mnew;
                sfac[srow] = scale;
            }
        }
        __syncthreads();

        // acc = acc*scale + P @ V  (thread owns column d, rows rg..rg+31)
        #pragma unroll
        for (int r = 0; r < 32; r++) acc[r] *= sfac[rg + r];
        #pragma unroll 4
        for (int j4 = 0; j4 < 16; j4++) {
            float vv0 = Vs[(j4 * 4 + 0) * VDIM + d];
            float vv1 = Vs[(j4 * 4 + 1) * VDIM + d];
            float vv2 = Vs[(j4 * 4 + 2) * VDIM + d];
            float vv3 = Vs[(j4 * 4 + 3) * VDIM + d];
            #pragma unroll
            for (int r = 0; r < 32; r++) {
                float4 p = *(const float4*)&Ps[(rg + r) * 68 + j4 * 4];
                acc[r] += p.x * vv0 + p.y * vv1 + p.z * vv2 + p.w * vv3;
            }
        }
    }

    #pragma unroll
    for (int r = 0; r < 32; r++) {
        float l = lrow[rg + r];
        g_O[(g * SQ + q0 + rg + r) * VDIM + d] = acc[r] / l;
    }
}

// ============================================================================
// Epilogue: x = O[2h] - lam*O[2h+1]; RMSNorm over 128; * subln_g * (1-lam_init)
// grid (S, H), 128 threads
// ============================================================================
__global__ __launch_bounds__(128) void epi_kernel(const float* __restrict__ subg)
{
    const int s = blockIdx.x, h = blockIdx.y, d = threadIdx.x;
    const float lam = g_lam;
    float a = g_O[((2 * h) * SQ + s) * VDIM + d];
    float b = g_O[((2 * h + 1) * SQ + s) * VDIM + d];
    float x = a - lam * b;

    float v = x * x;
    #pragma unroll
    for (int o = 16; o > 0; o >>= 1) v += __shfl_xor_sync(0xffffffffu, v, o);
    __shared__ float ws[4];
    if ((d & 31) == 0) ws[d >> 5] = v;
    __syncthreads();
    float tot = ws[0] + ws[1] + ws[2] + ws[3];
    float rms = rsqrtf(tot * (1.f / 128.f) + 1e-5f);

    g_X[s * ED + h * VDIM + d] = x * rms * subg[d] * (1.f - LAMBDA_INIT);
}

// ============================================================================
// launch
// ============================================================================
extern "C" void kernel_launch(void* const* d_in, const int* in_sizes, int n_in,
                              void* d_out, int out_size)
{
    (void)in_sizes; (void)n_in; (void)out_size;
    const float* query = (const float*)d_in[0];
    const float* key   = (const float*)d_in[1];
    const float* value = (const float*)d_in[2];
    // d_in[3] = rel_pos (unused, always 0)
    const unsigned char* mask = (const unsigned char*)d_in[4];
    const float* Wq  = (const float*)d_in[5];
    const float* Wk  = (const float*)d_in[6];
    const float* Wv  = (const float*)d_in[7];
    const float* Wo  = (const float*)d_in[8];
    const float* lq1 = (const float*)d_in[9];
    const float* lk1 = (const float*)d_in[10];
    const float* lq2 = (const float*)d_in[11];
    const float* lk2 = (const float*)d_in[12];
    const float* subg = (const float*)d_in[13];
    float* out = (float*)d_out;

    const int attn_smem = (3 * 64 * 68 + 64 * 128 + 3 * 64) * (int)sizeof(float); // 85760
    cudaFuncSetAttribute(attn_kernel, cudaFuncAttributeMaxDynamicSharedMemorySize, attn_smem);

    dim3 gblk(16, 16);
    gemm_nt<<<gblk, 256>>>(query, Wq, nullptr, 0, 1);
    gemm_nt<<<gblk, 256>>>(key,   Wk, nullptr, 0, 2);
    gemm_nt<<<gblk, 256>>>(value, Wv, nullptr, 0, 3);
    lam_kernel<<<1, 64>>>(lq1, lk1, lq2, lk2);
    attn_kernel<<<dim3(32, 32), 256, attn_smem>>>(mask);
    epi_kernel<<<dim3(SQ, NH), 128>>>(subg);
    gemm_nt<<<gblk, 256>>>(nullptr, Wo, out, 1, 0);
}

// round 3
// speedup vs baseline: 3.2569x; 2.2682x over previous
#include <cuda_runtime.h>

#define SQ   2048
#define ED   2048
#define NH   16
#define NG   32      // 2*H query/key heads
#define HDIM 64      // differential head dim
#define VDIM 128     // value head dim (2*HD)

static constexpr float LAMBDA_INIT = 0.78360576653162444f;

// ---- device scratch (static: no runtime allocation allowed) ----
__device__ float g_Q[SQ * ED];
__device__ float g_K[SQ * ED];
__device__ float g_V[SQ * ED];
__device__ float g_O[NG * SQ * VDIM];   // per-QK-head attention outputs
__device__ float g_X[SQ * ED];          // combined/normalized attention (S, E)
__device__ float g_lam;

__device__ __forceinline__ unsigned f2tf(float x) {
    unsigned r;
    asm("cvt.rna.tf32.f32 %0, %1;" : "=r"(r) : "f"(x));
    return r;
}

__device__ __forceinline__ void mma_tf32(float c[4], const unsigned a[4], const unsigned b[2]) {
    asm volatile(
        "mma.sync.aligned.m16n8k8.row.col.f32.tf32.tf32.f32 "
        "{%0,%1,%2,%3}, {%4,%5,%6,%7}, {%8,%9}, {%0,%1,%2,%3};"
        : "+f"(c[0]), "+f"(c[1]), "+f"(c[2]), "+f"(c[3])
        : "r"(a[0]), "r"(a[1]), "r"(a[2]), "r"(a[3]), "r"(b[0]), "r"(b[1]));
}

// ============================================================================
// TF32 tensor-core GEMM (NT): C[m,n] = sum_k A[m,k] * W[n,k], M=N=K=2048
// ============================================================================
__global__ __launch_bounds__(256) void gemm_nt(const float* __restrict__ Aext,
                                               const float* __restrict__ W,
                                               float* __restrict__ Cext,
                                               int a_tag, int c_tag)
{
    const float* A = (a_tag == 0) ? Aext : g_X;
    float* C = Cext;
    if (c_tag == 1) C = g_Q;
    else if (c_tag == 2) C = g_K;
    else if (c_tag == 3) C = g_V;

    __shared__ unsigned As[128][36];
    __shared__ unsigned Bs[128][36];

    const int t    = threadIdx.x;
    const int m0   = blockIdx.y * 128;
    const int n0   = blockIdx.x * 128;
    const int wid  = t >> 5;
    const int lane = t & 31;
    const int wm   = (wid >> 2) * 64;
    const int wn   = (wid & 3) * 32;
    const int grp  = lane >> 2;
    const int qid  = lane & 3;

    float acc[4][4][4];
    #pragma unroll
    for (int mi = 0; mi < 4; mi++)
        #pragma unroll
        for (int ni = 0; ni < 4; ni++)
            #pragma unroll
            for (int x = 0; x < 4; x++) acc[mi][ni][x] = 0.f;

    float4 ra[4], rb[4];
    #pragma unroll
    for (int i = 0; i < 4; i++) {
        int lin = t + 256 * i;
        int r = lin >> 3, c = (lin & 7) * 4;
        ra[i] = *(const float4*)(A + (m0 + r) * ED + c);
        rb[i] = *(const float4*)(W + (n0 + r) * ED + c);
    }

    const int NT = ED / 32;
    for (int kt = 0; kt < NT; kt++) {
        #pragma unroll
        for (int i = 0; i < 4; i++) {
            int lin = t + 256 * i;
            int r = lin >> 3, c = (lin & 7) * 4;
            As[r][c + 0] = f2tf(ra[i].x); As[r][c + 1] = f2tf(ra[i].y);
            As[r][c + 2] = f2tf(ra[i].z); As[r][c + 3] = f2tf(ra[i].w);
            Bs[r][c + 0] = f2tf(rb[i].x); Bs[r][c + 1] = f2tf(rb[i].y);
            Bs[r][c + 2] = f2tf(rb[i].z); Bs[r][c + 3] = f2tf(rb[i].w);
        }
        __syncthreads();

        if (kt + 1 < NT) {
            int k0 = (kt + 1) * 32;
            #pragma unroll
            for (int i = 0; i < 4; i++) {
                int lin = t + 256 * i;
                int r = lin >> 3, c = (lin & 7) * 4;
                ra[i] = *(const float4*)(A + (m0 + r) * ED + k0 + c);
                rb[i] = *(const float4*)(W + (n0 + r) * ED + k0 + c);
            }
        }

        #pragma unroll
        for (int ks = 0; ks < 4; ks++) {
            unsigned af[4][4], bf[4][2];
            #pragma unroll
            for (int mi = 0; mi < 4; mi++) {
                int r = wm + mi * 16 + grp;
                af[mi][0] = As[r][ks * 8 + qid];
                af[mi][1] = As[r + 8][ks * 8 + qid];
                af[mi][2] = As[r][ks * 8 + qid + 4];
                af[mi][3] = As[r + 8][ks * 8 + qid + 4];
            }
            #pragma unroll
            for (int ni = 0; ni < 4; ni++) {
                int r = wn + ni * 8 + grp;
                bf[ni][0] = Bs[r][ks * 8 + qid];
                bf[ni][1] = Bs[r][ks * 8 + qid + 4];
            }
            #pragma unroll
            for (int mi = 0; mi < 4; mi++)
                #pragma unroll
                for (int ni = 0; ni < 4; ni++)
                    mma_tf32(acc[mi][ni], af[mi], bf[ni]);
        }
        __syncthreads();
    }

    #pragma unroll
    for (int mi = 0; mi < 4; mi++) {
        #pragma unroll
        for (int ni = 0; ni < 4; ni++) {
            int row = m0 + wm + mi * 16 + grp;
            int col = n0 + wn + ni * 8 + 2 * qid;
            *(float2*)&C[row * ED + col]       = make_float2(acc[mi][ni][0], acc[mi][ni][1]);
            *(float2*)&C[(row + 8) * ED + col] = make_float2(acc[mi][ni][2], acc[mi][ni][3]);
        }
    }
}

// ============================================================================
// lambda_full
// ============================================================================
__global__ void lam_kernel(const float* __restrict__ lq1, const float* __restrict__ lk1,
                           const float* __restrict__ lq2, const float* __restrict__ lk2)
{
    int lane = threadIdx.x;  // 64 threads
    float p1 = lq1[lane] * lk1[lane];
    float p2 = lq2[lane] * lk2[lane];
    #pragma unroll
    for (int o = 16; o > 0; o >>= 1) {
        p1 += __shfl_xor_sync(0xffffffffu, p1, o);
        p2 += __shfl_xor_sync(0xffffffffu, p2, o);
    }
    __shared__ float s1w[2], s2w[2];
    if ((lane & 31) == 0) { s1w[lane >> 5] = p1; s2w[lane >> 5] = p2; }
    __syncthreads();
    if (lane == 0)
        g_lam = expf(s1w[0] + s1w[1]) - expf(s2w[0] + s2w[1]) + LAMBDA_INIT;
}

// ============================================================================
// Tensor-core flash attention (tf32 mma, FA2-style register softmax).
// Block: 128 threads (4 warps), 64 query rows of one QK-head g.
// Warp w owns query rows [w*16, w*16+16). Scores/O stay in mma accumulators.
// ============================================================================
__global__ __launch_bounds__(128, 2) void attn_kernel(const unsigned char* __restrict__ mask)
{
    extern __shared__ unsigned smu[];
    unsigned* Qs = smu;                    // 64 x 68 (tf32)
    unsigned* Ks = Qs + 64 * 68;           // 64 x 68 (tf32)
    unsigned* Ps = Ks + 64 * 68;           // 64 x 68 (tf32)
    unsigned* Vs = Ps + 64 * 68;           // 64 x 132 (tf32)
    float*    Ms = (float*)(Vs + 64 * 132); // 64 mask addends

    const int g    = blockIdx.y;
    const int h    = g >> 1;
    const int q0   = blockIdx.x * 64;
    const int t    = threadIdx.x;
    const int lane = t & 31;
    const int grp  = lane >> 2;
    const int qid  = lane & 3;
    const int wq   = (t >> 5) * 16;

    // stage Q tile (scaled by hd^-0.5), tf32
    for (int i = t; i < 64 * 16; i += 128) {
        int r = i >> 4, c = (i & 15) * 4;
        float4 v = *(const float4*)&g_Q[(q0 + r) * ED + g * HDIM + c];
        unsigned* dst = &Qs[r * 68 + c];
        dst[0] = f2tf(v.x * 0.125f); dst[1] = f2tf(v.y * 0.125f);
        dst[2] = f2tf(v.z * 0.125f); dst[3] = f2tf(v.w * 0.125f);
    }
    __syncthreads();

    // Q fragments held in registers for the whole kernel
    unsigned qf[8][4];
    #pragma unroll
    for (int ks = 0; ks < 8; ks++) {
        qf[ks][0] = Qs[(wq + grp) * 68 + 8 * ks + qid];
        qf[ks][1] = Qs[(wq + grp + 8) * 68 + 8 * ks + qid];
        qf[ks][2] = Qs[(wq + grp) * 68 + 8 * ks + qid + 4];
        qf[ks][3] = Qs[(wq + grp + 8) * 68 + 8 * ks + qid + 4];
    }

    float of[16][4];
    #pragma unroll
    for (int n = 0; n < 16; n++)
        #pragma unroll
        for (int x = 0; x < 4; x++) of[n][x] = 0.f;
    float m0 = -1e30f, m1 = -1e30f, l0 = 0.f, l1 = 0.f;

    for (int kt = 0; kt < SQ; kt += 64) {
        __syncthreads();
        // stage K tile (tf32)
        for (int i = t; i < 64 * 16; i += 128) {
            int r = i >> 4, c = (i & 15) * 4;
            float4 v = *(const float4*)&g_K[(kt + r) * ED + g * HDIM + c];
            unsigned* dst = &Ks[r * 68 + c];
            dst[0] = f2tf(v.x); dst[1] = f2tf(v.y); dst[2] = f2tf(v.z); dst[3] = f2tf(v.w);
        }
        // stage V tile (tf32)
        for (int i = t; i < 64 * 32; i += 128) {
            int r = i >> 5, c = (i & 31) * 4;
            float4 v = *(const float4*)&g_V[(kt + r) * ED + h * VDIM + c];
            unsigned* dst = &Vs[r * 132 + c];
            dst[0] = f2tf(v.x); dst[1] = f2tf(v.y); dst[2] = f2tf(v.z); dst[3] = f2tf(v.w);
        }
        if (t < 64) Ms[t] = mask[kt + t] ? -1e30f : 0.f;
        __syncthreads();

        // ---- scores = Q K^T (tf32 mma) ----
        float sc[8][4];
        #pragma unroll
        for (int n = 0; n < 8; n++)
            #pragma unroll
            for (int x = 0; x < 4; x++) sc[n][x] = 0.f;
        #pragma unroll
        for (int ks = 0; ks < 8; ks++) {
            unsigned kb[8][2];
            #pragma unroll
            for (int n = 0; n < 8; n++) {
                kb[n][0] = Ks[(8 * n + grp) * 68 + 8 * ks + qid];
                kb[n][1] = Ks[(8 * n + grp) * 68 + 8 * ks + qid + 4];
            }
            #pragma unroll
            for (int n = 0; n < 8; n++) mma_tf32(sc[n], qf[ks], kb[n]);
        }
        // mask addend
        #pragma unroll
        for (int n = 0; n < 8; n++) {
            float a0 = Ms[8 * n + 2 * qid], a1 = Ms[8 * n + 2 * qid + 1];
            sc[n][0] += a0; sc[n][1] += a1; sc[n][2] += a0; sc[n][3] += a1;
        }

        // ---- register online softmax (rows grp, grp+8) ----
        float mx0 = -1e30f, mx1 = -1e30f;
        #pragma unroll
        for (int n = 0; n < 8; n++) {
            mx0 = fmaxf(mx0, fmaxf(sc[n][0], sc[n][1]));
            mx1 = fmaxf(mx1, fmaxf(sc[n][2], sc[n][3]));
        }
        mx0 = fmaxf(mx0, __shfl_xor_sync(0xffffffffu, mx0, 1));
        mx0 = fmaxf(mx0, __shfl_xor_sync(0xffffffffu, mx0, 2));
        mx1 = fmaxf(mx1, __shfl_xor_sync(0xffffffffu, mx1, 1));
        mx1 = fmaxf(mx1, __shfl_xor_sync(0xffffffffu, mx1, 2));
        float mn0 = fmaxf(m0, mx0), mn1 = fmaxf(m1, mx1);
        float sum0 = 0.f, sum1 = 0.f;
        #pragma unroll
        for (int n = 0; n < 8; n++) {
            sc[n][0] = __expf(sc[n][0] - mn0); sum0 += sc[n][0];
            sc[n][1] = __expf(sc[n][1] - mn0); sum0 += sc[n][1];
            sc[n][2] = __expf(sc[n][2] - mn1); sum1 += sc[n][2];
            sc[n][3] = __expf(sc[n][3] - mn1); sum1 += sc[n][3];
        }
        sum0 += __shfl_xor_sync(0xffffffffu, sum0, 1);
        sum0 += __shfl_xor_sync(0xffffffffu, sum0, 2);
        sum1 += __shfl_xor_sync(0xffffffffu, sum1, 1);
        sum1 += __shfl_xor_sync(0xffffffffu, sum1, 2);
        float f0 = __expf(m0 - mn0), f1 = __expf(m1 - mn1);
        l0 = l0 * f0 + sum0; l1 = l1 * f1 + sum1;
        m0 = mn0; m1 = mn1;
        #pragma unroll
        for (int n = 0; n < 16; n++) {
            of[n][0] *= f0; of[n][1] *= f0; of[n][2] *= f1; of[n][3] *= f1;
        }

        // ---- P: accum layout -> A-operand layout via padded smem ----
        #pragma unroll
        for (int n = 0; n < 8; n++) {
            *(uint2*)&Ps[(wq + grp) * 68 + 8 * n + 2 * qid]     =
                make_uint2(f2tf(sc[n][0]), f2tf(sc[n][1]));
            *(uint2*)&Ps[(wq + grp + 8) * 68 + 8 * n + 2 * qid] =
                make_uint2(f2tf(sc[n][2]), f2tf(sc[n][3]));
        }
        __syncwarp();

        // ---- O += P V (tf32 mma) ----
        #pragma unroll
        for (int ks = 0; ks < 8; ks++) {
            unsigned pa[4];
            pa[0] = Ps[(wq + grp) * 68 + 8 * ks + qid];
            pa[1] = Ps[(wq + grp + 8) * 68 + 8 * ks + qid];
            pa[2] = Ps[(wq + grp) * 68 + 8 * ks + qid + 4];
            pa[3] = Ps[(wq + grp + 8) * 68 + 8 * ks + qid + 4];
            #pragma unroll
            for (int n = 0; n < 16; n++) {
                unsigned vb[2];
                vb[0] = Vs[(8 * ks + qid) * 132 + 8 * n + grp];
                vb[1] = Vs[(8 * ks + qid + 4) * 132 + 8 * n + grp];
                mma_tf32(of[n], pa, vb);
            }
        }
        __syncwarp();
    }

    float r0 = 1.f / l0, r1 = 1.f / l1;
    #pragma unroll
    for (int n = 0; n < 16; n++) {
        int row = q0 + wq + grp, col = 8 * n + 2 * qid;
        *(float2*)&g_O[(g * SQ + row) * VDIM + col]       =
            make_float2(of[n][0] * r0, of[n][1] * r0);
        *(float2*)&g_O[(g * SQ + row + 8) * VDIM + col]   =
            make_float2(of[n][2] * r1, of[n][3] * r1);
    }
}

// ============================================================================
// Epilogue: x = O[2h] - lam*O[2h+1]; RMSNorm over 128; * subln_g * (1-lam_init)
// ============================================================================
__global__ __launch_bounds__(128) void epi_kernel(const float* __restrict__ subg)
{
    const int s = blockIdx.x, h = blockIdx.y, d = threadIdx.x;
    const float lam = g_lam;
    float a = g_O[((2 * h) * SQ + s) * VDIM + d];
    float b = g_O[((2 * h + 1) * SQ + s) * VDIM + d];
    float x = a - lam * b;

    float v = x * x;
    #pragma unroll
    for (int o = 16; o > 0; o >>= 1) v += __shfl_xor_sync(0xffffffffu, v, o);
    __shared__ float ws[4];
    if ((d & 31) == 0) ws[d >> 5] = v;
    __syncthreads();
    float tot = ws[0] + ws[1] + ws[2] + ws[3];
    float rms = rsqrtf(tot * (1.f / 128.f) + 1e-5f);

    g_X[s * ED + h * VDIM + d] = x * rms * subg[d] * (1.f - LAMBDA_INIT);
}

// ============================================================================
// launch
// ============================================================================
extern "C" void kernel_launch(void* const* d_in, const int* in_sizes, int n_in,
                              void* d_out, int out_size)
{
    (void)in_sizes; (void)n_in; (void)out_size;
    const float* query = (const float*)d_in[0];
    const float* key   = (const float*)d_in[1];
    const float* value = (const float*)d_in[2];
    const unsigned char* mask = (const unsigned char*)d_in[4];
    const float* Wq  = (const float*)d_in[5];
    const float* Wk  = (const float*)d_in[6];
    const float* Wv  = (const float*)d_in[7];
    const float* Wo  = (const float*)d_in[8];
    const float* lq1 = (const float*)d_in[9];
    const float* lk1 = (const float*)d_in[10];
    const float* lq2 = (const float*)d_in[11];
    const float* lk2 = (const float*)d_in[12];
    const float* subg = (const float*)d_in[13];
    float* out = (float*)d_out;

    const int attn_smem = (3 * 64 * 68 + 64 * 132) * (int)sizeof(unsigned) + 64 * (int)sizeof(float); // 86272
    cudaFuncSetAttribute(attn_kernel, cudaFuncAttributeMaxDynamicSharedMemorySize, attn_smem);

    dim3 gblk(16, 16);
    gemm_nt<<<gblk, 256>>>(query, Wq, nullptr, 0, 1);
    gemm_nt<<<gblk, 256>>>(key,   Wk, nullptr, 0, 2);
    gemm_nt<<<gblk, 256>>>(value, Wv, nullptr, 0, 3);
    lam_kernel<<<1, 64>>>(lq1, lk1, lq2, lk2);
    attn_kernel<<<dim3(32, 32), 128, attn_smem>>>(mask);
    epi_kernel<<<dim3(SQ, NH), 128>>>(subg);
    gemm_nt<<<gblk, 256>>>(nullptr, Wo, out, 1, 0);
}

// round 4
// speedup vs baseline: 3.2630x; 1.0019x over previous
#include <cuda_runtime.h>

#define SQ   2048
#define ED   2048
#define NH   16
#define NG   32      // 2*H query/key heads
#define HDIM 64      // differential head dim
#define VDIM 128     // value head dim (2*HD)

static constexpr float LAMBDA_INIT = 0.78360576653162444f;

// ---- device scratch (static: no runtime allocation allowed) ----
__device__ float g_Q[SQ * ED];
__device__ float g_K[SQ * ED];
__device__ float g_V[SQ * ED];
__device__ float g_O[NG * SQ * VDIM];   // per-QK-head attention outputs
__device__ float g_X[SQ * ED];          // combined/normalized attention (S, E)
__device__ float g_lam;

__device__ __forceinline__ unsigned f2tf(float x) {
    unsigned r;
    asm("cvt.rna.tf32.f32 %0, %1;" : "=r"(r) : "f"(x));
    return r;
}

__device__ __forceinline__ void mma_tf32(float c[4], const unsigned a[4], const unsigned b[2]) {
    asm volatile(
        "mma.sync.aligned.m16n8k8.row.col.f32.tf32.tf32.f32 "
        "{%0,%1,%2,%3}, {%4,%5,%6,%7}, {%8,%9}, {%0,%1,%2,%3};"
        : "+f"(c[0]), "+f"(c[1]), "+f"(c[2]), "+f"(c[3])
        : "r"(a[0]), "r"(a[1]), "r"(a[2]), "r"(a[3]), "r"(b[0]), "r"(b[1]));
}

// ============================================================================
// TF32 tensor-core GEMM (NT): C[m,n] = sum_k A[m,k] * W[n,k], M=N=K=2048
// ============================================================================
__global__ __launch_bounds__(256) void gemm_nt(const float* __restrict__ Aext,
                                               const float* __restrict__ W,
                                               float* __restrict__ Cext,
                                               int a_tag, int c_tag)
{
    const float* A = (a_tag == 0) ? Aext : g_X;
    float* C = Cext;
    if (c_tag == 1) C = g_Q;
    else if (c_tag == 2) C = g_K;
    else if (c_tag == 3) C = g_V;

    __shared__ unsigned As[128][36];
    __shared__ unsigned Bs[128][36];

    const int t    = threadIdx.x;
    const int m0   = blockIdx.y * 128;
    const int n0   = blockIdx.x * 128;
    const int wid  = t >> 5;
    const int lane = t & 31;
    const int wm   = (wid >> 2) * 64;
    const int wn   = (wid & 3) * 32;
    const int grp  = lane >> 2;
    const int qid  = lane & 3;

    float acc[4][4][4];
    #pragma unroll
    for (int mi = 0; mi < 4; mi++)
        #pragma unroll
        for (int ni = 0; ni < 4; ni++)
            #pragma unroll
            for (int x = 0; x < 4; x++) acc[mi][ni][x] = 0.f;

    float4 ra[4], rb[4];
    #pragma unroll
    for (int i = 0; i < 4; i++) {
        int lin = t + 256 * i;
        int r = lin >> 3, c = (lin & 7) * 4;
        ra[i] = *(const float4*)(A + (m0 + r) * ED + c);
        rb[i] = *(const float4*)(W + (n0 + r) * ED + c);
    }

    const int NT = ED / 32;
    for (int kt = 0; kt < NT; kt++) {
        #pragma unroll
        for (int i = 0; i < 4; i++) {
            int lin = t + 256 * i;
            int r = lin >> 3, c = (lin & 7) * 4;
            As[r][c + 0] = f2tf(ra[i].x); As[r][c + 1] = f2tf(ra[i].y);
            As[r][c + 2] = f2tf(ra[i].z); As[r][c + 3] = f2tf(ra[i].w);
            Bs[r][c + 0] = f2tf(rb[i].x); Bs[r][c + 1] = f2tf(rb[i].y);
            Bs[r][c + 2] = f2tf(rb[i].z); Bs[r][c + 3] = f2tf(rb[i].w);
        }
        __syncthreads();

        if (kt + 1 < NT) {
            int k0 = (kt + 1) * 32;
            #pragma unroll
            for (int i = 0; i < 4; i++) {
                int lin = t + 256 * i;
                int r = lin >> 3, c = (lin & 7) * 4;
                ra[i] = *(const float4*)(A + (m0 + r) * ED + k0 + c);
                rb[i] = *(const float4*)(W + (n0 + r) * ED + k0 + c);
            }
        }

        #pragma unroll
        for (int ks = 0; ks < 4; ks++) {
            unsigned af[4][4], bf[4][2];
            #pragma unroll
            for (int mi = 0; mi < 4; mi++) {
                int r = wm + mi * 16 + grp;
                af[mi][0] = As[r][ks * 8 + qid];
                af[mi][1] = As[r + 8][ks * 8 + qid];
                af[mi][2] = As[r][ks * 8 + qid + 4];
                af[mi][3] = As[r + 8][ks * 8 + qid + 4];
            }
            #pragma unroll
            for (int ni = 0; ni < 4; ni++) {
                int r = wn + ni * 8 + grp;
                bf[ni][0] = Bs[r][ks * 8 + qid];
                bf[ni][1] = Bs[r][ks * 8 + qid + 4];
            }
            #pragma unroll
            for (int mi = 0; mi < 4; mi++)
                #pragma unroll
                for (int ni = 0; ni < 4; ni++)
                    mma_tf32(acc[mi][ni], af[mi], bf[ni]);
        }
        __syncthreads();
    }

    #pragma unroll
    for (int mi = 0; mi < 4; mi++) {
        #pragma unroll
        for (int ni = 0; ni < 4; ni++) {
            int row = m0 + wm + mi * 16 + grp;
            int col = n0 + wn + ni * 8 + 2 * qid;
            *(float2*)&C[row * ED + col]       = make_float2(acc[mi][ni][0], acc[mi][ni][1]);
            *(float2*)&C[(row + 8) * ED + col] = make_float2(acc[mi][ni][2], acc[mi][ni][3]);
        }
    }
}

// ============================================================================
// lambda_full
// ============================================================================
__global__ void lam_kernel(const float* __restrict__ lq1, const float* __restrict__ lk1,
                           const float* __restrict__ lq2, const float* __restrict__ lk2)
{
    int lane = threadIdx.x;  // 64 threads
    float p1 = lq1[lane] * lk1[lane];
    float p2 = lq2[lane] * lk2[lane];
    #pragma unroll
    for (int o = 16; o > 0; o >>= 1) {
        p1 += __shfl_xor_sync(0xffffffffu, p1, o);
        p2 += __shfl_xor_sync(0xffffffffu, p2, o);
    }
    __shared__ float s1w[2], s2w[2];
    if ((lane & 31) == 0) { s1w[lane >> 5] = p1; s2w[lane >> 5] = p2; }
    __syncthreads();
    if (lane == 0)
        g_lam = expf(s1w[0] + s1w[1]) - expf(s2w[0] + s2w[1]) + LAMBDA_INIT;
}

// ============================================================================
// Tensor-core flash attention (tf32 mma, FA2-style register softmax).
// Block: 128 threads (4 warps), 64 query rows of one QK-head g.
// Warp w owns query rows [w*16, w*16+16). Scores/O stay in mma accumulators.
// ============================================================================
__global__ __launch_bounds__(128, 2) void attn_kernel(const unsigned char* __restrict__ mask)
{
    extern __shared__ unsigned smu[];
    unsigned* Qs = smu;                    // 64 x 68 (tf32)
    unsigned* Ks = Qs + 64 * 68;           // 64 x 68 (tf32)
    unsigned* Ps = Ks + 64 * 68;           // 64 x 68 (tf32)
    unsigned* Vs = Ps + 64 * 68;           // 64 x 132 (tf32)
    float*    Ms = (float*)(Vs + 64 * 132); // 64 mask addends

    const int g    = blockIdx.y;
    const int h    = g >> 1;
    const int q0   = blockIdx.x * 64;
    const int t    = threadIdx.x;
    const int lane = t & 31;
    const int grp  = lane >> 2;
    const int qid  = lane & 3;
    const int wq   = (t >> 5) * 16;

    // stage Q tile (scaled by hd^-0.5), tf32
    for (int i = t; i < 64 * 16; i += 128) {
        int r = i >> 4, c = (i & 15) * 4;
        float4 v = *(const float4*)&g_Q[(q0 + r) * ED + g * HDIM + c];
        unsigned* dst = &Qs[r * 68 + c];
        dst[0] = f2tf(v.x * 0.125f); dst[1] = f2tf(v.y * 0.125f);
        dst[2] = f2tf(v.z * 0.125f); dst[3] = f2tf(v.w * 0.125f);
    }
    __syncthreads();

    // Q fragments held in registers for the whole kernel
    unsigned qf[8][4];
    #pragma unroll
    for (int ks = 0; ks < 8; ks++) {
        qf[ks][0] = Qs[(wq + grp) * 68 + 8 * ks + qid];
        qf[ks][1] = Qs[(wq + grp + 8) * 68 + 8 * ks + qid];
        qf[ks][2] = Qs[(wq + grp) * 68 + 8 * ks + qid + 4];
        qf[ks][3] = Qs[(wq + grp + 8) * 68 + 8 * ks + qid + 4];
    }

    float of[16][4];
    #pragma unroll
    for (int n = 0; n < 16; n++)
        #pragma unroll
        for (int x = 0; x < 4; x++) of[n][x] = 0.f;
    float m0 = -1e30f, m1 = -1e30f, l0 = 0.f, l1 = 0.f;

    for (int kt = 0; kt < SQ; kt += 64) {
        __syncthreads();
        // stage K tile (tf32)
        for (int i = t; i < 64 * 16; i += 128) {
            int r = i >> 4, c = (i & 15) * 4;
            float4 v = *(const float4*)&g_K[(kt + r) * ED + g * HDIM + c];
            unsigned* dst = &Ks[r * 68 + c];
            dst[0] = f2tf(v.x); dst[1] = f2tf(v.y); dst[2] = f2tf(v.z); dst[3] = f2tf(v.w);
        }
        // stage V tile (tf32)
        for (int i = t; i < 64 * 32; i += 128) {
            int r = i >> 5, c = (i & 31) * 4;
            float4 v = *(const float4*)&g_V[(kt + r) * ED + h * VDIM + c];
            unsigned* dst = &Vs[r * 132 + c];
            dst[0] = f2tf(v.x); dst[1] = f2tf(v.y); dst[2] = f2tf(v.z); dst[3] = f2tf(v.w);
        }
        if (t < 64) Ms[t] = mask[kt + t] ? -1e30f : 0.f;
        __syncthreads();

        // ---- scores = Q K^T (tf32 mma) ----
        float sc[8][4];
        #pragma unroll
        for (int n = 0; n < 8; n++)
            #pragma unroll
            for (int x = 0; x < 4; x++) sc[n][x] = 0.f;
        #pragma unroll
        for (int ks = 0; ks < 8; ks++) {
            unsigned kb[8][2];
            #pragma unroll
            for (int n = 0; n < 8; n++) {
                kb[n][0] = Ks[(8 * n + grp) * 68 + 8 * ks + qid];
                kb[n][1] = Ks[(8 * n + grp) * 68 + 8 * ks + qid + 4];
            }
            #pragma unroll
            for (int n = 0; n < 8; n++) mma_tf32(sc[n], qf[ks], kb[n]);
        }
        // mask addend
        #pragma unroll
        for (int n = 0; n < 8; n++) {
            float a0 = Ms[8 * n + 2 * qid], a1 = Ms[8 * n + 2 * qid + 1];
            sc[n][0] += a0; sc[n][1] += a1; sc[n][2] += a0; sc[n][3] += a1;
        }

        // ---- register online softmax (rows grp, grp+8) ----
        float mx0 = -1e30f, mx1 = -1e30f;
        #pragma unroll
        for (int n = 0; n < 8; n++) {
            mx0 = fmaxf(mx0, fmaxf(sc[n][0], sc[n][1]));
            mx1 = fmaxf(mx1, fmaxf(sc[n][2], sc[n][3]));
        }
        mx0 = fmaxf(mx0, __shfl_xor_sync(0xffffffffu, mx0, 1));
        mx0 = fmaxf(mx0, __shfl_xor_sync(0xffffffffu, mx0, 2));
        mx1 = fmaxf(mx1, __shfl_xor_sync(0xffffffffu, mx1, 1));
        mx1 = fmaxf(mx1, __shfl_xor_sync(0xffffffffu, mx1, 2));
        float mn0 = fmaxf(m0, mx0), mn1 = fmaxf(m1, mx1);
        float sum0 = 0.f, sum1 = 0.f;
        #pragma unroll
        for (int n = 0; n < 8; n++) {
            sc[n][0] = __expf(sc[n][0] - mn0); sum0 += sc[n][0];
            sc[n][1] = __expf(sc[n][1] - mn0); sum0 += sc[n][1];
            sc[n][2] = __expf(sc[n][2] - mn1); sum1 += sc[n][2];
            sc[n][3] = __expf(sc[n][3] - mn1); sum1 += sc[n][3];
        }
        sum0 += __shfl_xor_sync(0xffffffffu, sum0, 1);
        sum0 += __shfl_xor_sync(0xffffffffu, sum0, 2);
        sum1 += __shfl_xor_sync(0xffffffffu, sum1, 1);
        sum1 += __shfl_xor_sync(0xffffffffu, sum1, 2);
        float f0 = __expf(m0 - mn0), f1 = __expf(m1 - mn1);
        l0 = l0 * f0 + sum0; l1 = l1 * f1 + sum1;
        m0 = mn0; m1 = mn1;
        #pragma unroll
        for (int n = 0; n < 16; n++) {
            of[n][0] *= f0; of[n][1] *= f0; of[n][2] *= f1; of[n][3] *= f1;
        }

        // ---- P: accum layout -> A-operand layout via padded smem ----
        #pragma unroll
        for (int n = 0; n < 8; n++) {
            *(uint2*)&Ps[(wq + grp) * 68 + 8 * n + 2 * qid]     =
                make_uint2(f2tf(sc[n][0]), f2tf(sc[n][1]));
            *(uint2*)&Ps[(wq + grp + 8) * 68 + 8 * n + 2 * qid] =
                make_uint2(f2tf(sc[n][2]), f2tf(sc[n][3]));
        }
        __syncwarp();

        // ---- O += P V (tf32 mma) ----
        #pragma unroll
        for (int ks = 0; ks < 8; ks++) {
            unsigned pa[4];
            pa[0] = Ps[(wq + grp) * 68 + 8 * ks + qid];
            pa[1] = Ps[(wq + grp + 8) * 68 + 8 * ks + qid];
            pa[2] = Ps[(wq + grp) * 68 + 8 * ks + qid + 4];
            pa[3] = Ps[(wq + grp + 8) * 68 + 8 * ks + qid + 4];
            #pragma unroll
            for (int n = 0; n < 16; n++) {
                unsigned vb[2];
                vb[0] = Vs[(8 * ks + qid) * 132 + 8 * n + grp];
                vb[1] = Vs[(8 * ks + qid + 4) * 132 + 8 * n + grp];
                mma_tf32(of[n], pa, vb);
            }
        }
        __syncwarp();
    }

    float r0 = 1.f / l0, r1 = 1.f / l1;
    #pragma unroll
    for (int n = 0; n < 16; n++) {
        int row = q0 + wq + grp, col = 8 * n + 2 * qid;
        *(float2*)&g_O[(g * SQ + row) * VDIM + col]       =
            make_float2(of[n][0] * r0, of[n][1] * r0);
        *(float2*)&g_O[(g * SQ + row + 8) * VDIM + col]   =
            make_float2(of[n][2] * r1, of[n][3] * r1);
    }
}

// ============================================================================
// Epilogue: x = O[2h] - lam*O[2h+1]; RMSNorm over 128; * subln_g * (1-lam_init)
// ============================================================================
__global__ __launch_bounds__(128) void epi_kernel(const float* __restrict__ subg)
{
    const int s = blockIdx.x, h = blockIdx.y, d = threadIdx.x;
    const float lam = g_lam;
    float a = g_O[((2 * h) * SQ + s) * VDIM + d];
    float b = g_O[((2 * h + 1) * SQ + s) * VDIM + d];
    float x = a - lam * b;

    float v = x * x;
    #pragma unroll
    for (int o = 16; o > 0; o >>= 1) v += __shfl_xor_sync(0xffffffffu, v, o);
    __shared__ float ws[4];
    if ((d & 31) == 0) ws[d >> 5] = v;
    __syncthreads();
    float tot = ws[0] + ws[1] + ws[2] + ws[3];
    float rms = rsqrtf(tot * (1.f / 128.f) + 1e-5f);

    g_X[s * ED + h * VDIM + d] = x * rms * subg[d] * (1.f - LAMBDA_INIT);
}

// ============================================================================
// launch
// ============================================================================
extern "C" void kernel_launch(void* const* d_in, const int* in_sizes, int n_in,
                              void* d_out, int out_size)
{
    (void)in_sizes; (void)n_in; (void)out_size;
    const float* query = (const float*)d_in[0];
    const float* key   = (const float*)d_in[1];
    const float* value = (const float*)d_in[2];
    const unsigned char* mask = (const unsigned char*)d_in[4];
    const float* Wq  = (const float*)d_in[5];
    const float* Wk  = (const float*)d_in[6];
    const float* Wv  = (const float*)d_in[7];
    const float* Wo  = (const float*)d_in[8];
    const float* lq1 = (const float*)d_in[9];
    const float* lk1 = (const float*)d_in[10];
    const float* lq2 = (const float*)d_in[11];
    const float* lk2 = (const float*)d_in[12];
    const float* subg = (const float*)d_in[13];
    float* out = (float*)d_out;

    const int attn_smem = (3 * 64 * 68 + 64 * 132) * (int)sizeof(unsigned) + 64 * (int)sizeof(float); // 86272
    cudaFuncSetAttribute(attn_kernel, cudaFuncAttributeMaxDynamicSharedMemorySize, attn_smem);

    dim3 gblk(16, 16);
    gemm_nt<<<gblk, 256>>>(query, Wq, nullptr, 0, 1);
    gemm_nt<<<gblk, 256>>>(key,   Wk, nullptr, 0, 2);
    gemm_nt<<<gblk, 256>>>(value, Wv, nullptr, 0, 3);
    lam_kernel<<<1, 64>>>(lq1, lk1, lq2, lk2);
    attn_kernel<<<dim3(32, 32), 128, attn_smem>>>(mask);
    epi_kernel<<<dim3(SQ, NH), 128>>>(subg);
    gemm_nt<<<gblk, 256>>>(nullptr, Wo, out, 1, 0);
}